// round 1
// baseline (speedup 1.0000x reference)
#include <cuda_runtime.h>

// SNN (snntorch Leaky, subtract reset) XOR net:
//   cur = x @ w1^T           [B,4]   (time-invariant)
//   per t: m1 = b*m1 + cur - (m1_prev>1); spk1 = (m1>1)
//          out = spk1 @ w2^T; m2 = b*m2 + out - (m2_prev>1); spk2 = (m2>1)
//   output spikes [T, B, 1] fp32 (0/1)
//
// Memory-bound: 8 MB read + 84 MB write. One thread = 4 batch elements so
// each timestep store is STG.128 and x loads are LDG.128.

#define T_STEPS 20
#define BETA 0.9f
#define THR 1.0f

__global__ void __launch_bounds__(256) snn_xornet_kernel(
    const float* __restrict__ x,    // [B,2]
    const float* __restrict__ w1,   // [4,2]
    const float* __restrict__ w2,   // [1,4]
    float* __restrict__ out,        // [T,B]
    int B)
{
    const int i = blockIdx.x * blockDim.x + threadIdx.x;  // group of 4 elems
    const int b0 = i * 4;
    if (b0 >= B) return;

    // Broadcast weight loads (L1/L2 hit after first warp)
    float w1r[4][2];
#pragma unroll
    for (int h = 0; h < 4; h++) {
        w1r[h][0] = __ldg(&w1[2 * h + 0]);
        w1r[h][1] = __ldg(&w1[2 * h + 1]);
    }
    float w2r[4];
#pragma unroll
    for (int h = 0; h < 4; h++) w2r[h] = __ldg(&w2[h]);

    // x for 4 batch elements: 8 contiguous floats -> two float4
    const float4 xa = reinterpret_cast<const float4*>(x)[2 * i + 0];
    const float4 xb = reinterpret_cast<const float4*>(x)[2 * i + 1];
    const float xs[4][2] = {{xa.x, xa.y}, {xa.z, xa.w}, {xb.x, xb.y}, {xb.z, xb.w}};

    // cur = x @ w1^T, time-invariant
    float cur[4][4];
#pragma unroll
    for (int j = 0; j < 4; j++)
#pragma unroll
        for (int h = 0; h < 4; h++)
            cur[j][h] = fmaf(xs[j][0], w1r[h][0], xs[j][1] * w1r[h][1]);

    float m1[4][4];
    float m2[4];
#pragma unroll
    for (int j = 0; j < 4; j++) {
        m2[j] = 0.0f;
#pragma unroll
        for (int h = 0; h < 4; h++) m1[j][h] = 0.0f;
    }

    float4* out4 = reinterpret_cast<float4*>(out);
    const int Bq = B >> 2;

#pragma unroll
    for (int t = 0; t < T_STEPS; t++) {
        float o[4];
#pragma unroll
        for (int j = 0; j < 4; j++) {
            float acc = 0.0f;
#pragma unroll
            for (int h = 0; h < 4; h++) {
                const float reset = (m1[j][h] > THR) ? THR : 0.0f;
                const float m = fmaf(BETA, m1[j][h], cur[j][h]) - reset;
                m1[j][h] = m;
                acc += (m > THR) ? w2r[h] : 0.0f;   // spk1 @ w2^T
            }
            const float reset2 = (m2[j] > THR) ? THR : 0.0f;
            m2[j] = fmaf(BETA, m2[j], acc) - reset2;
            o[j] = (m2[j] > THR) ? 1.0f : 0.0f;
        }
        float4 v;
        v.x = o[0]; v.y = o[1]; v.z = o[2]; v.w = o[3];
        out4[(size_t)t * Bq + i] = v;
    }
}

extern "C" void kernel_launch(void* const* d_in, const int* in_sizes, int n_in,
                              void* d_out, int out_size) {
    const float* x  = (const float*)d_in[0];   // [B,2]
    const float* w1 = (const float*)d_in[1];   // [4,2]
    const float* w2 = (const float*)d_in[2];   // [1,4]
    float* out = (float*)d_out;                // [T,B,1]

    const int B = in_sizes[0] / 2;
    const int groups = B / 4;                  // B = 2^20, divisible by 4
    const int threads = 256;
    const int blocks = (groups + threads - 1) / threads;
    snn_xornet_kernel<<<blocks, threads>>>(x, w1, w2, out, B);
}